// round 2
// baseline (speedup 1.0000x reference)
#include <cuda_runtime.h>
#include <math.h>

// Problem constants
#define BATCH 64
#define SEQ   256
#define DM    512
#define DI    512
#define DS    16
#define DTRK  32
#define MROWS (BATCH*SEQ)   // 16384

// ----------------------------------------------------------------------------
// Scratch (device globals — no allocation allowed)
// ----------------------------------------------------------------------------
__device__ float g_xln[(size_t)MROWS * DM];       // 33.5 MB
__device__ float g_xz [(size_t)MROWS * 2 * DI];   // 67   MB  (xi | z)
__device__ float g_xc [(size_t)MROWS * DI];       // 33.5 MB
__device__ float g_proj[(size_t)MROWS * 64];      //  4   MB  (dtr|B|C)
__device__ float g_dt [(size_t)MROWS * DI];       // 33.5 MB
__device__ float g_y  [(size_t)MROWS * DI];       // 33.5 MB

// ----------------------------------------------------------------------------
// LayerNorm: one block per row, 128 threads, float4 per thread (cols = 512)
// Safe in-place: row values are register-resident before any write.
// ----------------------------------------------------------------------------
__global__ void ln_kernel(const float* __restrict__ x,
                          const float* __restrict__ g,
                          const float* __restrict__ b,
                          float* __restrict__ out)
{
    const int row = blockIdx.x;
    const int t   = threadIdx.x;
    const float4 v = reinterpret_cast<const float4*>(x + (size_t)row * DM)[t];

    float s  = v.x + v.y + v.z + v.w;
    float sq = v.x*v.x + v.y*v.y + v.z*v.z + v.w*v.w;
    #pragma unroll
    for (int o = 16; o > 0; o >>= 1) {
        s  += __shfl_xor_sync(0xffffffffu, s,  o);
        sq += __shfl_xor_sync(0xffffffffu, sq, o);
    }
    __shared__ float ss[4], ssq[4];
    const int w = t >> 5, l = t & 31;
    if (l == 0) { ss[w] = s; ssq[w] = sq; }
    __syncthreads();
    s  = ss[0] + ss[1] + ss[2] + ss[3];
    sq = ssq[0] + ssq[1] + ssq[2] + ssq[3];

    const float mean = s * (1.0f / DM);
    const float var  = sq * (1.0f / DM) - mean * mean;
    const float inv  = rsqrtf(var + 1e-5f);

    const float4 gg = reinterpret_cast<const float4*>(g)[t];
    const float4 bb = reinterpret_cast<const float4*>(b)[t];
    float4 o4;
    o4.x = (v.x - mean) * inv * gg.x + bb.x;
    o4.y = (v.y - mean) * inv * gg.y + bb.y;
    o4.z = (v.z - mean) * inv * gg.z + bb.z;
    o4.w = (v.w - mean) * inv * gg.w + bb.w;
    reinterpret_cast<float4*>(out + (size_t)row * DM)[t] = o4;
}

// ----------------------------------------------------------------------------
// Generic SMEM-tiled GEMM:  C[M,N] = A[M,K] * B[N,K]^T  (+ epilogue)
//   EPI 0: plain store
//   EPI 1: C += aux (residual, same layout/ldc as C)
//   EPI 2: C = softplus(C + aux[n])   (bias vector)
// All dims assumed divisible by tile sizes (true for this problem).
// ----------------------------------------------------------------------------
__device__ __forceinline__ float softplusf(float x) {
    return (x > 20.0f) ? x : log1pf(__expf(x));
}

template<int BM, int BN, int BK, int TM, int TN, int EPI>
__global__ void gemm_tn(const float* __restrict__ A,
                        const float* __restrict__ B,
                        const float* __restrict__ aux,
                        float* __restrict__ C,
                        int Mm, int Nn, int Kk,
                        int lda, int ldb, int ldc)
{
    constexpr int THREADS = (BM / TM) * (BN / TN);
    __shared__ float As[BK][BM];
    __shared__ float Bs[BK][BN];

    const int bm  = blockIdx.y * BM;
    const int bn  = blockIdx.x * BN;
    const int tid = threadIdx.x;

    constexpr int BNT = BN / TN;
    const int tcol = tid % BNT;
    const int trow = tid / BNT;

    // float4 load mapping
    constexpr int F4PR = BK / 4;                 // float4 per tile row
    const int aRow = tid / F4PR;
    const int aCol = (tid % F4PR) * 4;
    constexpr int A_STEP = THREADS / F4PR;       // tile rows per pass
    const int bRow = aRow;
    const int bCol = aCol;
    constexpr int B_STEP = A_STEP;

    float acc[TM][TN];
    #pragma unroll
    for (int i = 0; i < TM; i++)
        #pragma unroll
        for (int j = 0; j < TN; j++) acc[i][j] = 0.0f;

    for (int k0 = 0; k0 < Kk; k0 += BK) {
        #pragma unroll
        for (int r = 0; r < BM; r += A_STEP) {
            float4 v = *reinterpret_cast<const float4*>(
                &A[(size_t)(bm + r + aRow) * lda + k0 + aCol]);
            As[aCol + 0][r + aRow] = v.x;
            As[aCol + 1][r + aRow] = v.y;
            As[aCol + 2][r + aRow] = v.z;
            As[aCol + 3][r + aRow] = v.w;
        }
        #pragma unroll
        for (int r = 0; r < BN; r += B_STEP) {
            float4 v = *reinterpret_cast<const float4*>(
                &B[(size_t)(bn + r + bRow) * ldb + k0 + bCol]);
            Bs[bCol + 0][r + bRow] = v.x;
            Bs[bCol + 1][r + bRow] = v.y;
            Bs[bCol + 2][r + bRow] = v.z;
            Bs[bCol + 3][r + bRow] = v.w;
        }
        __syncthreads();

        #pragma unroll
        for (int kk = 0; kk < BK; kk++) {
            float ra[TM], rb[TN];
            #pragma unroll
            for (int i = 0; i < TM / 4; i++) {
                float4 v = *reinterpret_cast<const float4*>(&As[kk][trow * TM + i * 4]);
                ra[i*4+0] = v.x; ra[i*4+1] = v.y; ra[i*4+2] = v.z; ra[i*4+3] = v.w;
            }
            #pragma unroll
            for (int j = 0; j < TN / 4; j++) {
                float4 v = *reinterpret_cast<const float4*>(&Bs[kk][tcol * TN + j * 4]);
                rb[j*4+0] = v.x; rb[j*4+1] = v.y; rb[j*4+2] = v.z; rb[j*4+3] = v.w;
            }
            #pragma unroll
            for (int i = 0; i < TM; i++)
                #pragma unroll
                for (int j = 0; j < TN; j++)
                    acc[i][j] = fmaf(ra[i], rb[j], acc[i][j]);
        }
        __syncthreads();
    }

    // epilogue + vectorized store
    #pragma unroll
    for (int i = 0; i < TM; i++) {
        const int row = bm + trow * TM + i;
        #pragma unroll
        for (int j = 0; j < TN; j += 4) {
            const int col = bn + tcol * TN + j;
            float4 v;
            v.x = acc[i][j+0]; v.y = acc[i][j+1]; v.z = acc[i][j+2]; v.w = acc[i][j+3];
            if (EPI == 1) {
                float4 r = *reinterpret_cast<const float4*>(&aux[(size_t)row * ldc + col]);
                v.x += r.x; v.y += r.y; v.z += r.z; v.w += r.w;
            } else if (EPI == 2) {
                float4 bias = *reinterpret_cast<const float4*>(&aux[col]);
                v.x = softplusf(v.x + bias.x);
                v.y = softplusf(v.y + bias.y);
                v.z = softplusf(v.z + bias.z);
                v.w = softplusf(v.w + bias.w);
            }
            *reinterpret_cast<float4*>(&C[(size_t)row * ldc + col]) = v;
        }
    }
}

// ----------------------------------------------------------------------------
// Causal depthwise conv (width 4) + SiLU.
// xi = g_xz[:, 0:512].  grid (BATCH, 4 chunks of 64 steps), block 512 = one d each.
// ----------------------------------------------------------------------------
__global__ void conv_silu_kernel(const float* __restrict__ xz,
                                 const float* __restrict__ conv_w,
                                 const float* __restrict__ conv_b,
                                 float* __restrict__ xc)
{
    const int b  = blockIdx.x;
    const int kc = blockIdx.y;          // 0..3, 64 steps each
    const int c  = threadIdx.x;         // channel

    const float w0 = conv_w[c * 4 + 0];
    const float w1 = conv_w[c * 4 + 1];
    const float w2 = conv_w[c * 4 + 2];
    const float w3 = conv_w[c * 4 + 3];
    const float bias = conv_b[c];

    const float* xin = xz + (size_t)b * SEQ * (2 * DI) + c;
    float*       xo  = xc + (size_t)b * SEQ * DI + c;

    const int k0 = kc * 64;
    float x0 = (k0 - 3 >= 0) ? xin[(size_t)(k0 - 3) * (2 * DI)] : 0.0f;
    float x1 = (k0 - 2 >= 0) ? xin[(size_t)(k0 - 2) * (2 * DI)] : 0.0f;
    float x2 = (k0 - 1 >= 0) ? xin[(size_t)(k0 - 1) * (2 * DI)] : 0.0f;

    #pragma unroll 4
    for (int k = k0; k < k0 + 64; k++) {
        const float xk = xin[(size_t)k * (2 * DI)];
        float a = bias + x0 * w0 + x1 * w1 + x2 * w2 + xk * w3;
        a = a * (1.0f / (1.0f + __expf(-a)));   // SiLU
        xo[(size_t)k * DI] = a;
        x0 = x1; x1 = x2; x2 = xk;
    }
}

// ----------------------------------------------------------------------------
// Selective scan + gated epilogue:
//   h[s] = exp(dt*A[s])*h[s] + dt*x*B[s];  y = sum_s h[s]*C[s]
//   out = (y + x*Dp) * silu(z)
// grid (BATCH, 4 d-chunks of 128), block 128 threads = one d each.
// B/C staged through SMEM in 64-step chunks (broadcast reads).
// ----------------------------------------------------------------------------
__global__ void scan_kernel(const float* __restrict__ dt,
                            const float* __restrict__ xc,
                            const float* __restrict__ proj,
                            const float* __restrict__ xz,
                            const float* __restrict__ A_log,
                            const float* __restrict__ Dp,
                            float* __restrict__ y)
{
    const int b = blockIdx.x;
    const int d = blockIdx.y * 128 + threadIdx.x;

    __shared__ float sB[64][DS];
    __shared__ float sC[64][DS];

    float Av[DS];
    #pragma unroll
    for (int s = 0; s < DS; s++) Av[s] = -expf(A_log[d * DS + s]);

    float h[DS];
    #pragma unroll
    for (int s = 0; s < DS; s++) h[s] = 0.0f;

    const float dpv = Dp[d];

    for (int kc = 0; kc < SEQ / 64; kc++) {
        __syncthreads();
        for (int i = threadIdx.x; i < 64 * 32; i += 128) {
            const int kk = i >> 5;
            const int j  = i & 31;
            const float v = proj[(size_t)(b * SEQ + kc * 64 + kk) * 64 + 32 + j];
            if (j < DS) sB[kk][j] = v;
            else        sC[kk][j - DS] = v;
        }
        __syncthreads();

        for (int kk = 0; kk < 64; kk++) {
            const int m = b * SEQ + kc * 64 + kk;
            const float dtv = dt[(size_t)m * DI + d];
            const float xv  = xc[(size_t)m * DI + d];
            const float dtx = dtv * xv;
            float yv = 0.0f;
            #pragma unroll
            for (int s = 0; s < DS; s++) {
                const float dA = __expf(dtv * Av[s]);
                h[s] = fmaf(dA, h[s], dtx * sB[kk][s]);
                yv   = fmaf(h[s], sC[kk][s], yv);
            }
            const float zv = xz[(size_t)m * (2 * DI) + DI + d];
            const float sz = zv * (1.0f / (1.0f + __expf(-zv)));
            y[(size_t)m * DI + d] = (yv + xv * dpv) * sz;
        }
    }
}

// ----------------------------------------------------------------------------
// Launch
// ----------------------------------------------------------------------------
extern "C" void kernel_launch(void* const* d_in, const int* in_sizes, int n_in,
                              void* d_out, int out_size)
{
    const float* slots     = (const float*)d_in[0];
    const float* ln_g      = (const float*)d_in[1];
    const float* ln_b      = (const float*)d_in[2];
    const float* in_proj_w = (const float*)d_in[3];   // [1024, 512]
    const float* conv_w    = (const float*)d_in[4];   // [512, 4]
    const float* conv_b    = (const float*)d_in[5];   // [512]
    const float* x_proj_w  = (const float*)d_in[6];   // [64, 512]
    const float* dt_proj_w = (const float*)d_in[7];   // [512, 32]
    const float* dt_proj_b = (const float*)d_in[8];   // [512]
    const float* A_log     = (const float*)d_in[9];   // [512, 16]
    const float* Dp        = (const float*)d_in[10];  // [512]
    const float* out_proj_w= (const float*)d_in[11];  // [512, 512]
    const float* fln_g     = (const float*)d_in[12];
    const float* fln_b     = (const float*)d_in[13];
    float* out = (float*)d_out;

    // pointers to device-global scratch (kernels reference symbols directly,
    // but we need host-side addresses only for nothing — all symbol use is in-kernel)

    // 1) pre-LN
    ln_kernel<<<MROWS, 128>>>(slots, ln_g, ln_b, g_xln);

    // 2) in_proj: xz[16384,1024] = xln @ in_proj_w^T
    gemm_tn<128, 128, 16, 8, 8, 0><<<dim3(1024 / 128, MROWS / 128), 256>>>(
        g_xln, in_proj_w, nullptr, g_xz, MROWS, 1024, 512, 512, 512, 1024);

    // 3) causal conv + SiLU on xi = xz[:, :512]
    conv_silu_kernel<<<dim3(BATCH, 4), 512>>>(g_xz, conv_w, conv_b, g_xc);

    // 4) x_proj: proj[16384,64] = xc @ x_proj_w^T
    gemm_tn<128, 64, 16, 8, 4, 0><<<dim3(64 / 64, MROWS / 128), 256>>>(
        g_xc, x_proj_w, nullptr, g_proj, MROWS, 64, 512, 512, 512, 64);

    // 5) dt = softplus(dtr @ dt_proj_w^T + b); dtr = proj[:, :32] (lda = 64)
    gemm_tn<128, 128, 16, 8, 8, 2><<<dim3(512 / 128, MROWS / 128), 256>>>(
        g_proj, dt_proj_w, dt_proj_b, g_dt, MROWS, 512, 32, 64, 32, 512);

    // 6) selective scan + gated epilogue -> g_y
    scan_kernel<<<dim3(BATCH, 4), 128>>>(g_dt, g_xc, g_proj, g_xz, A_log, Dp, g_y);

    // 7) out_proj + residual -> d_out
    gemm_tn<128, 128, 16, 8, 8, 1><<<dim3(512 / 128, MROWS / 128), 256>>>(
        g_y, out_proj_w, slots, out, MROWS, 512, 512, 512, 512, 512);

    // 8) final LN in-place
    ln_kernel<<<MROWS, 128>>>(out, fln_g, fln_b, out);
}

// round 3
// speedup vs baseline: 1.2326x; 1.2326x over previous
#include <cuda_runtime.h>
#include <math.h>
#include <stdint.h>

// Problem constants
#define BATCH 64
#define SEQ   256
#define DM    512
#define DI    512
#define DS    16
#define MROWS (BATCH*SEQ)   // 16384

// ----------------------------------------------------------------------------
// Scratch (device globals — no allocation allowed)
// ----------------------------------------------------------------------------
__device__ float g_xln[(size_t)MROWS * DM];
__device__ float g_xz [(size_t)MROWS * 2 * DI];
__device__ float g_xc [(size_t)MROWS * DI];
__device__ float g_proj[(size_t)MROWS * 64];
__device__ float g_dt [(size_t)MROWS * DI];
__device__ float g_y  [(size_t)MROWS * DI];

// ----------------------------------------------------------------------------
// Helpers
// ----------------------------------------------------------------------------
__device__ __forceinline__ uint32_t f2tf32(float x) {
    uint32_t r;
    asm("cvt.rna.tf32.f32 %0, %1;" : "=r"(r) : "f"(x));
    return r;
}

__device__ __forceinline__ float softplusf(float x) {
    return (x > 20.0f) ? x : log1pf(__expf(x));
}

__device__ __forceinline__ void mma_tf32(float* c, const uint32_t* a, const uint32_t* b) {
    asm volatile(
        "mma.sync.aligned.m16n8k8.row.col.f32.tf32.tf32.f32 "
        "{%0,%1,%2,%3},{%4,%5,%6,%7},{%8,%9},{%0,%1,%2,%3};\n"
        : "+f"(c[0]), "+f"(c[1]), "+f"(c[2]), "+f"(c[3])
        : "r"(a[0]), "r"(a[1]), "r"(a[2]), "r"(a[3]), "r"(b[0]), "r"(b[1]));
}

// ----------------------------------------------------------------------------
// LayerNorm: one block per row, 128 threads, float4 per thread (cols = 512)
// ----------------------------------------------------------------------------
__global__ void ln_kernel(const float* __restrict__ x,
                          const float* __restrict__ g,
                          const float* __restrict__ b,
                          float* __restrict__ out)
{
    const int row = blockIdx.x;
    const int t   = threadIdx.x;
    const float4 v = reinterpret_cast<const float4*>(x + (size_t)row * DM)[t];

    float s  = v.x + v.y + v.z + v.w;
    float sq = v.x*v.x + v.y*v.y + v.z*v.z + v.w*v.w;
    #pragma unroll
    for (int o = 16; o > 0; o >>= 1) {
        s  += __shfl_xor_sync(0xffffffffu, s,  o);
        sq += __shfl_xor_sync(0xffffffffu, sq, o);
    }
    __shared__ float ss[4], ssq[4];
    const int w = t >> 5, l = t & 31;
    if (l == 0) { ss[w] = s; ssq[w] = sq; }
    __syncthreads();
    s  = ss[0] + ss[1] + ss[2] + ss[3];
    sq = ssq[0] + ssq[1] + ssq[2] + ssq[3];

    const float mean = s * (1.0f / DM);
    const float var  = sq * (1.0f / DM) - mean * mean;
    const float inv  = rsqrtf(var + 1e-5f);

    const float4 gg = reinterpret_cast<const float4*>(g)[t];
    const float4 bb = reinterpret_cast<const float4*>(b)[t];
    float4 o4;
    o4.x = (v.x - mean) * inv * gg.x + bb.x;
    o4.y = (v.y - mean) * inv * gg.y + bb.y;
    o4.z = (v.z - mean) * inv * gg.z + bb.z;
    o4.w = (v.w - mean) * inv * gg.w + bb.w;
    reinterpret_cast<float4*>(out + (size_t)row * DM)[t] = o4;
}

// ----------------------------------------------------------------------------
// TF32x2 tensor-core GEMM:  C[M,N] = A[M,K] * B[N,K]^T (+ epilogue)
//   full-fp32-accuracy via A/B split into tf32 hi + lo, 3 MMAs per tile.
//   EPI 0: plain store; 1: += aux (residual); 2: softplus(+bias aux[n]).
// Tiles: block = BM x BN (BM=WM*32, BN=WN*32), 8 warps, warp tile 32x32.
// SMEM per k-slab (BK=32): hi/lo interleaved, row stride 72 words.
// ----------------------------------------------------------------------------
#define KPAD 72   // 32 k-values * 2 (hi,lo) + 8 pad words

template<int BM, int BN, int WM, int WN, int EPI>
__global__ __launch_bounds__(256, 2)
void gemm_tf32(const float* __restrict__ A,
               const float* __restrict__ B,
               const float* __restrict__ aux,
               float* __restrict__ C,
               int K, int lda, int ldb, int ldc)
{
    extern __shared__ uint32_t sm[];
    uint32_t* As = sm;               // [BM][KPAD]
    uint32_t* Bs = sm + BM * KPAD;   // [BN][KPAD]

    const int tid  = threadIdx.x;
    const int lane = tid & 31;
    const int wid  = tid >> 5;
    const int wm   = wid % WM;
    const int wn   = wid / WM;
    const int g    = lane >> 2;
    const int tg   = lane & 3;

    const int bm = blockIdx.y * BM;
    const int bn = blockIdx.x * BN;

    float acc[2][4][4];
    #pragma unroll
    for (int mt = 0; mt < 2; mt++)
        #pragma unroll
        for (int nt = 0; nt < 4; nt++)
            #pragma unroll
            for (int i = 0; i < 4; i++) acc[mt][nt][i] = 0.0f;

    for (int k0 = 0; k0 < K; k0 += 32) {
        // ---- stage A ----
        #pragma unroll
        for (int it = 0; it < BM / 32; it++) {
            const int idx = tid + it * 256;
            const int r   = idx >> 3;
            const int c   = (idx & 7) * 4;
            const float4 v = *reinterpret_cast<const float4*>(
                &A[(size_t)(bm + r) * lda + k0 + c]);
            uint32_t h0 = f2tf32(v.x), h1 = f2tf32(v.y), h2 = f2tf32(v.z), h3 = f2tf32(v.w);
            uint32_t l0 = f2tf32(v.x - __uint_as_float(h0));
            uint32_t l1 = f2tf32(v.y - __uint_as_float(h1));
            uint32_t l2 = f2tf32(v.z - __uint_as_float(h2));
            uint32_t l3 = f2tf32(v.w - __uint_as_float(h3));
            uint32_t* p = &As[r * KPAD + 2 * c];
            reinterpret_cast<uint4*>(p)[0] = make_uint4(h0, l0, h1, l1);
            reinterpret_cast<uint4*>(p)[1] = make_uint4(h2, l2, h3, l3);
        }
        // ---- stage B ----
        #pragma unroll
        for (int it = 0; it < BN / 32; it++) {
            const int idx = tid + it * 256;
            const int r   = idx >> 3;
            const int c   = (idx & 7) * 4;
            const float4 v = *reinterpret_cast<const float4*>(
                &B[(size_t)(bn + r) * ldb + k0 + c]);
            uint32_t h0 = f2tf32(v.x), h1 = f2tf32(v.y), h2 = f2tf32(v.z), h3 = f2tf32(v.w);
            uint32_t l0 = f2tf32(v.x - __uint_as_float(h0));
            uint32_t l1 = f2tf32(v.y - __uint_as_float(h1));
            uint32_t l2 = f2tf32(v.z - __uint_as_float(h2));
            uint32_t l3 = f2tf32(v.w - __uint_as_float(h3));
            uint32_t* p = &Bs[r * KPAD + 2 * c];
            reinterpret_cast<uint4*>(p)[0] = make_uint4(h0, l0, h1, l1);
            reinterpret_cast<uint4*>(p)[1] = make_uint4(h2, l2, h3, l3);
        }
        __syncthreads();

        // ---- compute 4 k8-steps ----
        #pragma unroll
        for (int ks = 0; ks < 4; ks++) {
            uint32_t ah[2][4], al[2][4], bh[4][2], bl[4][2];
            #pragma unroll
            for (int mt = 0; mt < 2; mt++) {
                const int r = wm * 32 + mt * 16 + g;
                const uint32_t* p0 = &As[r * KPAD + 2 * (ks * 8 + tg)];
                const uint32_t* p1 = p0 + 8 * KPAD;
                uint2 u;
                u = *reinterpret_cast<const uint2*>(p0);     ah[mt][0] = u.x; al[mt][0] = u.y;
                u = *reinterpret_cast<const uint2*>(p0 + 8); ah[mt][2] = u.x; al[mt][2] = u.y;
                u = *reinterpret_cast<const uint2*>(p1);     ah[mt][1] = u.x; al[mt][1] = u.y;
                u = *reinterpret_cast<const uint2*>(p1 + 8); ah[mt][3] = u.x; al[mt][3] = u.y;
            }
            #pragma unroll
            for (int nt = 0; nt < 4; nt++) {
                const int n = wn * 32 + nt * 8 + g;
                const uint32_t* p = &Bs[n * KPAD + 2 * (ks * 8 + tg)];
                uint2 u;
                u = *reinterpret_cast<const uint2*>(p);     bh[nt][0] = u.x; bl[nt][0] = u.y;
                u = *reinterpret_cast<const uint2*>(p + 8); bh[nt][1] = u.x; bl[nt][1] = u.y;
            }
            #pragma unroll
            for (int mt = 0; mt < 2; mt++)
                #pragma unroll
                for (int nt = 0; nt < 4; nt++) {
                    mma_tf32(acc[mt][nt], ah[mt], bh[nt]);
                    mma_tf32(acc[mt][nt], ah[mt], bl[nt]);
                    mma_tf32(acc[mt][nt], al[mt], bh[nt]);
                }
        }
        __syncthreads();
    }

    // ---- epilogue ----
    #pragma unroll
    for (int mt = 0; mt < 2; mt++) {
        const int r0 = bm + wm * 32 + mt * 16 + g;
        const int r1 = r0 + 8;
        #pragma unroll
        for (int nt = 0; nt < 4; nt++) {
            const int col = bn + wn * 32 + nt * 8 + 2 * tg;
            float2 v0 = make_float2(acc[mt][nt][0], acc[mt][nt][1]);
            float2 v1 = make_float2(acc[mt][nt][2], acc[mt][nt][3]);
            if (EPI == 1) {
                float2 a0 = *reinterpret_cast<const float2*>(&aux[(size_t)r0 * ldc + col]);
                float2 a1 = *reinterpret_cast<const float2*>(&aux[(size_t)r1 * ldc + col]);
                v0.x += a0.x; v0.y += a0.y; v1.x += a1.x; v1.y += a1.y;
            } else if (EPI == 2) {
                float2 bi = *reinterpret_cast<const float2*>(&aux[col]);
                v0.x = softplusf(v0.x + bi.x); v0.y = softplusf(v0.y + bi.y);
                v1.x = softplusf(v1.x + bi.x); v1.y = softplusf(v1.y + bi.y);
            }
            *reinterpret_cast<float2*>(&C[(size_t)r0 * ldc + col]) = v0;
            *reinterpret_cast<float2*>(&C[(size_t)r1 * ldc + col]) = v1;
        }
    }
}

// ----------------------------------------------------------------------------
// Causal depthwise conv (width 4) + SiLU
// ----------------------------------------------------------------------------
__global__ void conv_silu_kernel(const float* __restrict__ xz,
                                 const float* __restrict__ conv_w,
                                 const float* __restrict__ conv_b,
                                 float* __restrict__ xc)
{
    const int b  = blockIdx.x;
    const int kc = blockIdx.y;
    const int c  = threadIdx.x;

    const float w0 = conv_w[c * 4 + 0];
    const float w1 = conv_w[c * 4 + 1];
    const float w2 = conv_w[c * 4 + 2];
    const float w3 = conv_w[c * 4 + 3];
    const float bias = conv_b[c];

    const float* xin = xz + (size_t)b * SEQ * (2 * DI) + c;
    float*       xo  = xc + (size_t)b * SEQ * DI + c;

    const int k0 = kc * 64;
    float x0 = (k0 - 3 >= 0) ? xin[(size_t)(k0 - 3) * (2 * DI)] : 0.0f;
    float x1 = (k0 - 2 >= 0) ? xin[(size_t)(k0 - 2) * (2 * DI)] : 0.0f;
    float x2 = (k0 - 1 >= 0) ? xin[(size_t)(k0 - 1) * (2 * DI)] : 0.0f;

    #pragma unroll 4
    for (int k = k0; k < k0 + 64; k++) {
        const float xk = xin[(size_t)k * (2 * DI)];
        float a = bias + x0 * w0 + x1 * w1 + x2 * w2 + xk * w3;
        a = a * (1.0f / (1.0f + __expf(-a)));
        xo[(size_t)k * DI] = a;
        x0 = x1; x1 = x2; x2 = xk;
    }
}

// ----------------------------------------------------------------------------
// Selective scan + gated epilogue
// ----------------------------------------------------------------------------
__global__ void scan_kernel(const float* __restrict__ dt,
                            const float* __restrict__ xc,
                            const float* __restrict__ proj,
                            const float* __restrict__ xz,
                            const float* __restrict__ A_log,
                            const float* __restrict__ Dp,
                            float* __restrict__ y)
{
    const int b = blockIdx.x;
    const int d = blockIdx.y * 128 + threadIdx.x;

    __shared__ float sB[64][DS];
    __shared__ float sC[64][DS];

    float Av[DS];
    #pragma unroll
    for (int s = 0; s < DS; s++) Av[s] = -expf(A_log[d * DS + s]);

    float h[DS];
    #pragma unroll
    for (int s = 0; s < DS; s++) h[s] = 0.0f;

    const float dpv = Dp[d];

    for (int kc = 0; kc < SEQ / 64; kc++) {
        __syncthreads();
        for (int i = threadIdx.x; i < 64 * 32; i += 128) {
            const int kk = i >> 5;
            const int j  = i & 31;
            const float v = proj[(size_t)(b * SEQ + kc * 64 + kk) * 64 + 32 + j];
            if (j < DS) sB[kk][j] = v;
            else        sC[kk][j - DS] = v;
        }
        __syncthreads();

        for (int kk = 0; kk < 64; kk++) {
            const int m = b * SEQ + kc * 64 + kk;
            const float dtv = dt[(size_t)m * DI + d];
            const float xv  = xc[(size_t)m * DI + d];
            const float dtx = dtv * xv;
            float yv = 0.0f;
            #pragma unroll
            for (int s = 0; s < DS; s++) {
                const float dA = __expf(dtv * Av[s]);
                h[s] = fmaf(dA, h[s], dtx * sB[kk][s]);
                yv   = fmaf(h[s], sC[kk][s], yv);
            }
            const float zv = xz[(size_t)m * (2 * DI) + DI + d];
            const float sz = zv * (1.0f / (1.0f + __expf(-zv)));
            y[(size_t)m * DI + d] = (yv + xv * dpv) * sz;
        }
    }
}

// ----------------------------------------------------------------------------
// Launch
// ----------------------------------------------------------------------------
#define SMEM_G(BM, BN) ((BM + BN) * KPAD * 4)

extern "C" void kernel_launch(void* const* d_in, const int* in_sizes, int n_in,
                              void* d_out, int out_size)
{
    const float* slots     = (const float*)d_in[0];
    const float* ln_g      = (const float*)d_in[1];
    const float* ln_b      = (const float*)d_in[2];
    const float* in_proj_w = (const float*)d_in[3];
    const float* conv_w    = (const float*)d_in[4];
    const float* conv_b    = (const float*)d_in[5];
    const float* x_proj_w  = (const float*)d_in[6];
    const float* dt_proj_w = (const float*)d_in[7];
    const float* dt_proj_b = (const float*)d_in[8];
    const float* A_log     = (const float*)d_in[9];
    const float* Dp        = (const float*)d_in[10];
    const float* out_proj_w= (const float*)d_in[11];
    const float* fln_g     = (const float*)d_in[12];
    const float* fln_b     = (const float*)d_in[13];
    float* out = (float*)d_out;

    const int smA = SMEM_G(64, 128);   // 55296 bytes
    const int smB = SMEM_G(128, 64);

    cudaFuncSetAttribute((const void*)gemm_tf32<64, 128, 2, 4, 0>,
                         cudaFuncAttributeMaxDynamicSharedMemorySize, smA);
    cudaFuncSetAttribute((const void*)gemm_tf32<64, 128, 2, 4, 1>,
                         cudaFuncAttributeMaxDynamicSharedMemorySize, smA);
    cudaFuncSetAttribute((const void*)gemm_tf32<64, 128, 2, 4, 2>,
                         cudaFuncAttributeMaxDynamicSharedMemorySize, smA);
    cudaFuncSetAttribute((const void*)gemm_tf32<128, 64, 4, 2, 0>,
                         cudaFuncAttributeMaxDynamicSharedMemorySize, smB);

    // 1) pre-LN
    ln_kernel<<<MROWS, 128>>>(slots, ln_g, ln_b, g_xln);

    // 2) in_proj: xz[16384,1024] = xln @ in_proj_w^T
    gemm_tf32<64, 128, 2, 4, 0><<<dim3(1024 / 128, MROWS / 64), 256, smA>>>(
        g_xln, in_proj_w, nullptr, g_xz, 512, 512, 512, 1024);

    // 3) causal conv + SiLU
    conv_silu_kernel<<<dim3(BATCH, 4), 512>>>(g_xz, conv_w, conv_b, g_xc);

    // 4) x_proj: proj[16384,64] = xc @ x_proj_w^T
    gemm_tf32<128, 64, 4, 2, 0><<<dim3(64 / 64, MROWS / 128), 256, smB>>>(
        g_xc, x_proj_w, nullptr, g_proj, 512, 512, 512, 64);

    // 5) dt = softplus(dtr @ dt_proj_w^T + b)
    gemm_tf32<64, 128, 2, 4, 2><<<dim3(512 / 128, MROWS / 64), 256, smA>>>(
        g_proj, dt_proj_w, dt_proj_b, g_dt, 32, 64, 32, 512);

    // 6) selective scan + gated epilogue
    scan_kernel<<<dim3(BATCH, 4), 128>>>(g_dt, g_xc, g_proj, g_xz, A_log, Dp, g_y);

    // 7) out_proj + residual
    gemm_tf32<64, 128, 2, 4, 1><<<dim3(512 / 128, MROWS / 64), 256, smA>>>(
        g_y, out_proj_w, slots, out, 512, 512, 512, 512);

    // 8) final LN in-place
    ln_kernel<<<MROWS, 128>>>(out, fln_g, fln_b, out);
}

// round 4
// speedup vs baseline: 9.2501x; 7.5044x over previous
#include <cuda_runtime.h>
#include <cuda_bf16.h>
#include <math.h>
#include <stdint.h>

// Problem constants
#define BATCH 64
#define SEQ   256
#define DM    512
#define DI    512
#define DS    16
#define MROWS (BATCH*SEQ)   // 16384

// ----------------------------------------------------------------------------
// Scratch (device globals — no allocation allowed)
// Packed format: per fp32 element one uint32 = (bf16 hi | bf16 lo<<16),
// pair-interleaved along k: words 2p   = (hi[2p]  | hi[2p+1]<<16)
//                           words 2p+1 = (lo[2p]  | lo[2p+1]<<16)
// ----------------------------------------------------------------------------
__device__ __align__(128) uint32_t g_xln_pk[(size_t)MROWS * DM];
__device__ __align__(128) float    g_xz    [(size_t)MROWS * 2 * DI];
__device__ __align__(128) float    g_xc    [(size_t)MROWS * DI];
__device__ __align__(128) uint32_t g_xc_pk [(size_t)MROWS * DI];
__device__ __align__(128) float    g_proj  [(size_t)MROWS * 64];
__device__ __align__(128) uint32_t g_y_pk  [(size_t)MROWS * DI];
__device__ __align__(128) uint32_t g_wIn_pk [1024 * 512];
__device__ __align__(128) uint32_t g_wX_pk  [64 * 512];
__device__ __align__(128) uint32_t g_wOut_pk[512 * 512];

// ----------------------------------------------------------------------------
// Helpers
// ----------------------------------------------------------------------------
__device__ __forceinline__ float softplusf(float x) {
    return (x > 20.0f) ? x : log1pf(__expf(x));
}

// split two consecutive floats into (hi-pair word, lo-pair word)
__device__ __forceinline__ uint2 split_pair(float a, float b) {
    __nv_bfloat162 hv = __floats2bfloat162_rn(a, b);
    float2 hf = __bfloat1622float2(hv);
    __nv_bfloat162 lv = __floats2bfloat162_rn(a - hf.x, b - hf.y);
    uint2 r;
    r.x = *reinterpret_cast<uint32_t*>(&hv);
    r.y = *reinterpret_cast<uint32_t*>(&lv);
    return r;
}

// split one float into raw bf16 bits
__device__ __forceinline__ uint32_t split_one(float x) {
    __nv_bfloat16 h = __float2bfloat16_rn(x);
    float r = x - __bfloat162float(h);
    __nv_bfloat16 l = __float2bfloat16_rn(r);
    __nv_bfloat16_raw hr = h, lr = l;
    return (uint32_t)hr.x | ((uint32_t)lr.x << 16);
}

__device__ __forceinline__ void mma_bf16(float* c, const uint32_t* a, const uint32_t* b) {
    asm volatile(
        "mma.sync.aligned.m16n8k16.row.col.f32.bf16.bf16.f32 "
        "{%0,%1,%2,%3},{%4,%5,%6,%7},{%8,%9},{%0,%1,%2,%3};\n"
        : "+f"(c[0]), "+f"(c[1]), "+f"(c[2]), "+f"(c[3])
        : "r"(a[0]), "r"(a[1]), "r"(a[2]), "r"(a[3]), "r"(b[0]), "r"(b[1]));
}

__device__ __forceinline__ void cpasync16(void* smem_ptr, const void* gptr) {
    uint32_t s = (uint32_t)__cvta_generic_to_shared(smem_ptr);
    asm volatile("cp.async.cg.shared.global [%0], [%1], 16;\n" :: "r"(s), "l"(gptr));
}

// ----------------------------------------------------------------------------
// Weight pack: [R,C] fp32 row-major -> packed words (C even)
// ----------------------------------------------------------------------------
__global__ void pack_kernel(const float* __restrict__ in,
                            uint32_t* __restrict__ out, int npairs)
{
    int i = blockIdx.x * 256 + threadIdx.x;
    if (i < npairs) {
        uint2 w = split_pair(in[2 * i], in[2 * i + 1]);
        *reinterpret_cast<uint2*>(out + 2 * i) = w;
    }
}

// ----------------------------------------------------------------------------
// LayerNorm (fp32 out)
// ----------------------------------------------------------------------------
__global__ void ln_kernel(const float* __restrict__ x,
                          const float* __restrict__ g,
                          const float* __restrict__ b,
                          float* __restrict__ out)
{
    const int row = blockIdx.x;
    const int t   = threadIdx.x;
    const float4 v = reinterpret_cast<const float4*>(x + (size_t)row * DM)[t];

    float s  = v.x + v.y + v.z + v.w;
    float sq = v.x*v.x + v.y*v.y + v.z*v.z + v.w*v.w;
    #pragma unroll
    for (int o = 16; o > 0; o >>= 1) {
        s  += __shfl_xor_sync(0xffffffffu, s,  o);
        sq += __shfl_xor_sync(0xffffffffu, sq, o);
    }
    __shared__ float ss[4], ssq[4];
    const int w = t >> 5, l = t & 31;
    if (l == 0) { ss[w] = s; ssq[w] = sq; }
    __syncthreads();
    s  = ss[0] + ss[1] + ss[2] + ss[3];
    sq = ssq[0] + ssq[1] + ssq[2] + ssq[3];

    const float mean = s * (1.0f / DM);
    const float var  = sq * (1.0f / DM) - mean * mean;
    const float inv  = rsqrtf(var + 1e-5f);

    const float4 gg = reinterpret_cast<const float4*>(g)[t];
    const float4 bb = reinterpret_cast<const float4*>(b)[t];
    float4 o4;
    o4.x = (v.x - mean) * inv * gg.x + bb.x;
    o4.y = (v.y - mean) * inv * gg.y + bb.y;
    o4.z = (v.z - mean) * inv * gg.z + bb.z;
    o4.w = (v.w - mean) * inv * gg.w + bb.w;
    reinterpret_cast<float4*>(out + (size_t)row * DM)[t] = o4;
}

// LayerNorm with packed-bf16 output
__global__ void ln_pack_kernel(const float* __restrict__ x,
                               const float* __restrict__ g,
                               const float* __restrict__ b,
                               uint32_t* __restrict__ out)
{
    const int row = blockIdx.x;
    const int t   = threadIdx.x;
    const float4 v = reinterpret_cast<const float4*>(x + (size_t)row * DM)[t];

    float s  = v.x + v.y + v.z + v.w;
    float sq = v.x*v.x + v.y*v.y + v.z*v.z + v.w*v.w;
    #pragma unroll
    for (int o = 16; o > 0; o >>= 1) {
        s  += __shfl_xor_sync(0xffffffffu, s,  o);
        sq += __shfl_xor_sync(0xffffffffu, sq, o);
    }
    __shared__ float ss[4], ssq[4];
    const int w = t >> 5, l = t & 31;
    if (l == 0) { ss[w] = s; ssq[w] = sq; }
    __syncthreads();
    s  = ss[0] + ss[1] + ss[2] + ss[3];
    sq = ssq[0] + ssq[1] + ssq[2] + ssq[3];

    const float mean = s * (1.0f / DM);
    const float var  = sq * (1.0f / DM) - mean * mean;
    const float inv  = rsqrtf(var + 1e-5f);

    const float4 gg = reinterpret_cast<const float4*>(g)[t];
    const float4 bb = reinterpret_cast<const float4*>(b)[t];
    float o0 = (v.x - mean) * inv * gg.x + bb.x;
    float o1 = (v.y - mean) * inv * gg.y + bb.y;
    float o2 = (v.z - mean) * inv * gg.z + bb.z;
    float o3 = (v.w - mean) * inv * gg.w + bb.w;

    uint2 p0 = split_pair(o0, o1);
    uint2 p1 = split_pair(o2, o3);
    uint4 w4 = make_uint4(p0.x, p0.y, p1.x, p1.y);
    reinterpret_cast<uint4*>(out + (size_t)row * DM)[t] = w4;
}

// ----------------------------------------------------------------------------
// bf16x3 tensor-core GEMM: C[M,N] = A[M,K] * B[N,K]^T (+ epilogue)
// A, B pre-split packed bf16 (hi,lo) pair-interleaved.  2-stage cp.async.
// Warp tile 64x32 (MT=4 m16 tiles, NT=4 n8 tiles), block BM x BN.
//   EPI 0: plain fp32 store; 1: += aux (residual) then store.
// ----------------------------------------------------------------------------
#define GPITCH 40   // words per smem row: 32 data + 8 pad

template<int BM, int BN, int WM, int WN, int EPI>
__global__ void __launch_bounds__(WM * WN * 32)
gemm_bf16x3(const uint32_t* __restrict__ Apk,
            const uint32_t* __restrict__ Bpk,
            const float* __restrict__ aux,
            float* __restrict__ C,
            int K, int ldaw, int ldbw, int ldc)
{
    constexpr int THREADS = WM * WN * 32;
    constexpr int STAGE   = (BM + BN) * GPITCH;   // words per stage
    constexpr int AITERS  = BM * 8 / THREADS;
    constexpr int BITERS  = BN * 8 / THREADS;
    extern __shared__ uint32_t sm[];

    const int tid  = threadIdx.x;
    const int lane = tid & 31;
    const int wid  = tid >> 5;
    const int wm   = wid % WM;
    const int wn   = wid / WM;
    const int g    = lane >> 2;
    const int tg   = lane & 3;
    const int bm   = blockIdx.y * BM;
    const int bn   = blockIdx.x * BN;
    const int wr   = wm * 64;
    const int wc   = wn * 32;

    float acc[4][4][4];
    #pragma unroll
    for (int mt = 0; mt < 4; mt++)
        #pragma unroll
        for (int nt = 0; nt < 4; nt++)
            #pragma unroll
            for (int i = 0; i < 4; i++) acc[mt][nt][i] = 0.0f;

    const int nslab = K / 32;

    // ---- issue slab 0 ----
    {
        uint32_t* As = sm;
        uint32_t* Bs = sm + BM * GPITCH;
        #pragma unroll
        for (int it = 0; it < AITERS; it++) {
            int idx = tid + it * THREADS;
            int r = idx >> 3, c = (idx & 7) * 4;
            cpasync16(&As[r * GPITCH + c], Apk + (size_t)(bm + r) * ldaw + c);
        }
        #pragma unroll
        for (int it = 0; it < BITERS; it++) {
            int idx = tid + it * THREADS;
            int r = idx >> 3, c = (idx & 7) * 4;
            cpasync16(&Bs[r * GPITCH + c], Bpk + (size_t)(bn + r) * ldbw + c);
        }
        asm volatile("cp.async.commit_group;\n");
    }

    #pragma unroll 1
    for (int s = 0; s < nslab; s++) {
        if (s + 1 < nslab) {
            const int buf = (s + 1) & 1;
            const int k0w = (s + 1) * 32;
            uint32_t* As = sm + buf * STAGE;
            uint32_t* Bs = As + BM * GPITCH;
            #pragma unroll
            for (int it = 0; it < AITERS; it++) {
                int idx = tid + it * THREADS;
                int r = idx >> 3, c = (idx & 7) * 4;
                cpasync16(&As[r * GPITCH + c], Apk + (size_t)(bm + r) * ldaw + k0w + c);
            }
            #pragma unroll
            for (int it = 0; it < BITERS; it++) {
                int idx = tid + it * THREADS;
                int r = idx >> 3, c = (idx & 7) * 4;
                cpasync16(&Bs[r * GPITCH + c], Bpk + (size_t)(bn + r) * ldbw + k0w + c);
            }
            asm volatile("cp.async.commit_group;\n");
            asm volatile("cp.async.wait_group 1;\n");
        } else {
            asm volatile("cp.async.wait_group 0;\n");
        }
        __syncthreads();

        // ---- compute current slab ----
        {
            const uint32_t* As = sm + (s & 1) * STAGE;
            const uint32_t* Bs = As + BM * GPITCH;
            #pragma unroll
            for (int ks = 0; ks < 2; ks++) {
                const int kp0 = 2 * (tg + 8 * ks);
                const int kp1 = 2 * (tg + 4 + 8 * ks);
                uint32_t ah[4][4], al[4][4], bh[4][2], bl[4][2];
                #pragma unroll
                for (int mt = 0; mt < 4; mt++) {
                    const uint32_t* pr = As + (wr + mt * 16 + g) * GPITCH;
                    uint2 v;
                    v = *reinterpret_cast<const uint2*>(pr + kp0);
                    ah[mt][0] = v.x; al[mt][0] = v.y;
                    v = *reinterpret_cast<const uint2*>(pr + 8 * GPITCH + kp0);
                    ah[mt][1] = v.x; al[mt][1] = v.y;
                    v = *reinterpret_cast<const uint2*>(pr + kp1);
                    ah[mt][2] = v.x; al[mt][2] = v.y;
                    v = *reinterpret_cast<const uint2*>(pr + 8 * GPITCH + kp1);
                    ah[mt][3] = v.x; al[mt][3] = v.y;
                }
                #pragma unroll
                for (int nt = 0; nt < 4; nt++) {
                    const uint32_t* pn = Bs + (wc + nt * 8 + g) * GPITCH;
                    uint2 v;
                    v = *reinterpret_cast<const uint2*>(pn + kp0);
                    bh[nt][0] = v.x; bl[nt][0] = v.y;
                    v = *reinterpret_cast<const uint2*>(pn + kp1);
                    bh[nt][1] = v.x; bl[nt][1] = v.y;
                }
                #pragma unroll
                for (int mt = 0; mt < 4; mt++)
                    #pragma unroll
                    for (int nt = 0; nt < 4; nt++) {
                        mma_bf16(acc[mt][nt], ah[mt], bh[nt]);
                        mma_bf16(acc[mt][nt], ah[mt], bl[nt]);
                        mma_bf16(acc[mt][nt], al[mt], bh[nt]);
                    }
            }
        }
        __syncthreads();
    }

    // ---- epilogue ----
    #pragma unroll
    for (int mt = 0; mt < 4; mt++) {
        const int r0 = bm + wr + mt * 16 + g;
        const int r1 = r0 + 8;
        #pragma unroll
        for (int nt = 0; nt < 4; nt++) {
            const int col = bn + wc + nt * 8 + 2 * tg;
            float2 v0 = make_float2(acc[mt][nt][0], acc[mt][nt][1]);
            float2 v1 = make_float2(acc[mt][nt][2], acc[mt][nt][3]);
            if (EPI == 1) {
                float2 a0 = *reinterpret_cast<const float2*>(&aux[(size_t)r0 * ldc + col]);
                float2 a1 = *reinterpret_cast<const float2*>(&aux[(size_t)r1 * ldc + col]);
                v0.x += a0.x; v0.y += a0.y; v1.x += a1.x; v1.y += a1.y;
            }
            *reinterpret_cast<float2*>(&C[(size_t)r0 * ldc + col]) = v0;
            *reinterpret_cast<float2*>(&C[(size_t)r1 * ldc + col]) = v1;
        }
    }
}

// ----------------------------------------------------------------------------
// Causal depthwise conv (width 4) + SiLU; writes fp32 + packed bf16
// ----------------------------------------------------------------------------
__global__ void conv_silu_kernel(const float* __restrict__ xz,
                                 const float* __restrict__ conv_w,
                                 const float* __restrict__ conv_b,
                                 float* __restrict__ xc,
                                 uint32_t* __restrict__ xc_pk)
{
    const int b  = blockIdx.x;
    const int kc = blockIdx.y;
    const int c  = threadIdx.x;

    const float w0 = conv_w[c * 4 + 0];
    const float w1 = conv_w[c * 4 + 1];
    const float w2 = conv_w[c * 4 + 2];
    const float w3 = conv_w[c * 4 + 3];
    const float bias = conv_b[c];

    const float* xin = xz + (size_t)b * SEQ * (2 * DI) + c;

    const int k0 = kc * 64;
    float x0 = (k0 - 3 >= 0) ? xin[(size_t)(k0 - 3) * (2 * DI)] : 0.0f;
    float x1 = (k0 - 2 >= 0) ? xin[(size_t)(k0 - 2) * (2 * DI)] : 0.0f;
    float x2 = (k0 - 1 >= 0) ? xin[(size_t)(k0 - 1) * (2 * DI)] : 0.0f;

    #pragma unroll 4
    for (int k = k0; k < k0 + 64; k++) {
        const float xk = xin[(size_t)k * (2 * DI)];
        float a = bias + x0 * w0 + x1 * w1 + x2 * w2 + xk * w3;
        a = a * (1.0f / (1.0f + __expf(-a)));
        const size_t m = (size_t)b * SEQ + k;
        xc[m * DI + c] = a;

        uint32_t mine  = split_one(a);
        uint32_t other = __shfl_xor_sync(0xffffffffu, mine, 1);
        if ((c & 1) == 0) {
            uint32_t hw = (mine & 0xffffu) | (other << 16);
            uint32_t lw = (mine >> 16) | (other & 0xffff0000u);
            *reinterpret_cast<uint2*>(xc_pk + m * DI + c) = make_uint2(hw, lw);
        }
        x0 = x1; x1 = x2; x2 = xk;
    }
}

// ----------------------------------------------------------------------------
// Selective scan with fused dt-projection + gated epilogue; packed output
//   dt = softplus(dtr @ dt_w^T + dt_b); h,y recurrence; out = (y+x*Dp)*silu(z)
// grid (BATCH, 4 d-chunks of 128), block 128.
// ----------------------------------------------------------------------------
__global__ void scan_kernel(const float* __restrict__ proj,
                            const float* __restrict__ xc,
                            const float* __restrict__ xz,
                            const float* __restrict__ dt_w,
                            const float* __restrict__ dt_b,
                            const float* __restrict__ A_log,
                            const float* __restrict__ Dp,
                            uint32_t* __restrict__ ypk)
{
    const int b = blockIdx.x;
    const int d = blockIdx.y * 128 + threadIdx.x;

    __shared__ float sP[64][64];   // full proj rows: dtr[0:32] | B[32:48] | C[48:64]

    float W[32];
    #pragma unroll
    for (int k = 0; k < 32; k++) W[k] = dt_w[d * 32 + k];
    const float bias = dt_b[d];

    float Av[DS], h[DS];
    #pragma unroll
    for (int s = 0; s < DS; s++) { Av[s] = -expf(A_log[d * DS + s]); h[s] = 0.0f; }
    const float dpv = Dp[d];

    for (int kc = 0; kc < SEQ / 64; kc++) {
        __syncthreads();
        const float4* src = reinterpret_cast<const float4*>(
            proj + (size_t)(b * SEQ + kc * 64) * 64);
        float4* dst = reinterpret_cast<float4*>(&sP[0][0]);
        for (int i = threadIdx.x; i < 64 * 16; i += 128) dst[i] = src[i];
        __syncthreads();

        for (int kk = 0; kk < 64; kk++) {
            const size_t m = (size_t)b * SEQ + kc * 64 + kk;
            float acc0 = bias;
            #pragma unroll
            for (int k = 0; k < 32; k++) acc0 = fmaf(sP[kk][k], W[k], acc0);
            const float dtv = softplusf(acc0);

            const float xv  = xc[m * DI + d];
            const float dtx = dtv * xv;
            float yv = 0.0f;
            #pragma unroll
            for (int s = 0; s < DS; s++) {
                const float dA = __expf(dtv * Av[s]);
                h[s] = fmaf(dA, h[s], dtx * sP[kk][32 + s]);
                yv   = fmaf(h[s], sP[kk][48 + s], yv);
            }
            const float zv = xz[m * (2 * DI) + DI + d];
            const float sz = zv * (1.0f / (1.0f + __expf(-zv)));
            const float out = (yv + xv * dpv) * sz;

            uint32_t mine  = split_one(out);
            uint32_t other = __shfl_xor_sync(0xffffffffu, mine, 1);
            if ((d & 1) == 0) {
                uint32_t hw = (mine & 0xffffu) | (other << 16);
                uint32_t lw = (mine >> 16) | (other & 0xffff0000u);
                *reinterpret_cast<uint2*>(ypk + m * DI + d) = make_uint2(hw, lw);
            }
        }
    }
}

// ----------------------------------------------------------------------------
// Launch
// ----------------------------------------------------------------------------
extern "C" void kernel_launch(void* const* d_in, const int* in_sizes, int n_in,
                              void* d_out, int out_size)
{
    const float* slots     = (const float*)d_in[0];
    const float* ln_g      = (const float*)d_in[1];
    const float* ln_b      = (const float*)d_in[2];
    const float* in_proj_w = (const float*)d_in[3];
    const float* conv_w    = (const float*)d_in[4];
    const float* conv_b    = (const float*)d_in[5];
    const float* x_proj_w  = (const float*)d_in[6];
    const float* dt_proj_w = (const float*)d_in[7];
    const float* dt_proj_b = (const float*)d_in[8];
    const float* A_log     = (const float*)d_in[9];
    const float* Dp        = (const float*)d_in[10];
    const float* out_proj_w= (const float*)d_in[11];
    const float* fln_g     = (const float*)d_in[12];
    const float* fln_b     = (const float*)d_in[13];
    float* out = (float*)d_out;

    // device-global scratch addresses
    uint32_t *xln_pk, *xc_pk, *y_pk, *wIn, *wX, *wOut;
    float *xz, *xc, *proj;
    cudaGetSymbolAddress((void**)&xln_pk, g_xln_pk);
    cudaGetSymbolAddress((void**)&xz,     g_xz);
    cudaGetSymbolAddress((void**)&xc,     g_xc);
    cudaGetSymbolAddress((void**)&xc_pk,  g_xc_pk);
    cudaGetSymbolAddress((void**)&proj,   g_proj);
    cudaGetSymbolAddress((void**)&y_pk,   g_y_pk);
    cudaGetSymbolAddress((void**)&wIn,    g_wIn_pk);
    cudaGetSymbolAddress((void**)&wX,     g_wX_pk);
    cudaGetSymbolAddress((void**)&wOut,   g_wOut_pk);

    const int smBig   = 2 * 256 * GPITCH * 4;   // 81920 B (BM=BN=128)
    const int smSmall = 2 * 128 * GPITCH * 4;   // 40960 B (BM=BN=64)

    cudaFuncSetAttribute((const void*)gemm_bf16x3<128, 128, 2, 4, 0>,
                         cudaFuncAttributeMaxDynamicSharedMemorySize, smBig);
    cudaFuncSetAttribute((const void*)gemm_bf16x3<128, 128, 2, 4, 1>,
                         cudaFuncAttributeMaxDynamicSharedMemorySize, smBig);

    // 0) pack weights
    pack_kernel<<<(1024 * 512 / 2 + 255) / 256, 256>>>(in_proj_w,  wIn,  1024 * 512 / 2);
    pack_kernel<<<(64   * 512 / 2 + 255) / 256, 256>>>(x_proj_w,   wX,   64 * 512 / 2);
    pack_kernel<<<(512  * 512 / 2 + 255) / 256, 256>>>(out_proj_w, wOut, 512 * 512 / 2);

    // 1) pre-LN -> packed xln
    ln_pack_kernel<<<MROWS, 128>>>(slots, ln_g, ln_b, xln_pk);

    // 2) in_proj: xz[16384,1024] = xln @ in_proj_w^T   (fp32 out)
    gemm_bf16x3<128, 128, 2, 4, 0><<<dim3(1024 / 128, MROWS / 128), 256, smBig>>>(
        xln_pk, wIn, nullptr, xz, 512, 512, 512, 1024);

    // 3) causal conv + SiLU -> xc fp32 + packed
    conv_silu_kernel<<<dim3(BATCH, 4), 512>>>(xz, conv_w, conv_b, xc, xc_pk);

    // 4) x_proj: proj[16384,64] = xc @ x_proj_w^T  (fp32 out)
    gemm_bf16x3<64, 64, 1, 2, 0><<<dim3(1, MROWS / 64), 64, smSmall>>>(
        xc_pk, wX, nullptr, proj, 512, 512, 512, 64);

    // 5) scan with fused dt-projection -> packed y
    scan_kernel<<<dim3(BATCH, 4), 128>>>(proj, xc, xz, dt_proj_w, dt_proj_b,
                                         A_log, Dp, y_pk);

    // 6) out_proj + residual -> d_out (fp32)
    gemm_bf16x3<128, 128, 2, 4, 1><<<dim3(512 / 128, MROWS / 128), 256, smBig>>>(
        y_pk, wOut, slots, out, 512, 512, 512, 512);

    // 7) final LN in-place
    ln_kernel<<<MROWS, 128>>>(out, fln_g, fln_b, out);
}